// round 16
// baseline (speedup 1.0000x reference)
#include <cuda_runtime.h>
#include <cuda_fp16.h>
#include <cstdint>

#define BB 16
#define CC 512
#define HH 32
#define WW 32
#define NN 1024
#define C3 1536
#define NT4 64
#define TCOLS 1024
#define TAPS 36

typedef __half fp16;

// ---------------- scratch (device globals) -----------------------------------
__device__ fp16 g_Vh[(size_t)TAPS * CC * TCOLS];
__device__ fp16 g_Uh[(size_t)TAPS * C3 * CC];
__device__ fp16 g_Mw[(size_t)TAPS * C3 * TCOLS];
__device__ fp16 g_wfh[CC * C3];
__device__ fp16 g_Ah[(size_t)BB * CC * NN];
__device__ fp16 g_Bmh[(size_t)BB * CC * NN];
__device__ fp16 g_Dh[(size_t)BB * CC * NN];
__device__ fp16 g_xh[(size_t)BB * CC * NN];
__device__ float g_M[(size_t)BB * NN * NN];
__device__ fp16 g_Mh[(size_t)BB * NN * NN];
__device__ float g_S[(size_t)BB * CC * CC];
__device__ fp16 g_Sh[(size_t)BB * CC * CC];
__device__ fp16 g_spath[(size_t)BB * CC * NN];
__device__ fp16 g_chanh[(size_t)BB * CC * NN];

// ---------------- helpers ------------------------------------------------------
__device__ __forceinline__ uint32_t smem_u32(const void* p) {
    uint32_t a;
    asm("{ .reg .u64 t; cvta.to.shared.u64 t, %1; cvt.u32.u64 %0, t; }"
        : "=r"(a) : "l"(p));
    return a;
}
__device__ __forceinline__ void ldsm_x4(uint32_t* r, uint32_t addr) {
    asm volatile("ldmatrix.sync.aligned.m8n8.x4.shared.b16 {%0,%1,%2,%3}, [%4];"
                 : "=r"(r[0]), "=r"(r[1]), "=r"(r[2]), "=r"(r[3]) : "r"(addr));
}
__device__ __forceinline__ void ldsm_x4_t(uint32_t* r, uint32_t addr) {
    asm volatile("ldmatrix.sync.aligned.m8n8.x4.trans.shared.b16 {%0,%1,%2,%3}, [%4];"
                 : "=r"(r[0]), "=r"(r[1]), "=r"(r[2]), "=r"(r[3]) : "r"(addr));
}
__device__ __forceinline__ void mma16816(float* d, const uint32_t* a, const uint32_t* b) {
    asm volatile("mma.sync.aligned.m16n8k16.row.col.f32.f16.f16.f32 "
                 "{%0,%1,%2,%3}, {%4,%5,%6,%7}, {%8,%9}, {%0,%1,%2,%3};"
                 : "+f"(d[0]), "+f"(d[1]), "+f"(d[2]), "+f"(d[3])
                 : "r"(a[0]), "r"(a[1]), "r"(a[2]), "r"(a[3]), "r"(b[0]), "r"(b[1]));
}

// ---------------- GEMM ----------------------------------------------------------
// Block tile 128x128, BK=64, 128 threads (4 warps 2x2), warp tile 64x64.
// 3 stages x 32 KB = 96 KB/CTA; 2 CTAs co-resident.
#define TILEB 16384
#define STGB  (2 * TILEB)                // 32 KB
#define STAGES 3
#define GEMM_SMEM (STAGES * STGB)        // 96 KB

template<bool TR>
__device__ __forceinline__ void load_tile(uint32_t tb, const fp16* __restrict__ S,
                                          long rowbase, long ld, long k0, int tid) {
    if (!TR) {
        #pragma unroll
        for (int p = 0; p < 8; p++) {
            int row = (tid >> 3) + p * 16;
            int ch  = tid & 7;
            const void* g = (const void*)(S + (rowbase + row) * ld + k0 + ch * 8);
            uint32_t dst = tb + (uint32_t)(row * 128 + ((ch ^ (row & 7)) << 4));
            asm volatile("cp.async.cg.shared.global [%0], [%1], 16;"
                         :: "r"(dst), "l"(g) : "memory");
        }
    } else {
        #pragma unroll
        for (int p = 0; p < 8; p++) {
            int row = (tid >> 4) + p * 8;
            int ch  = tid & 15;
            const void* g = (const void*)(S + (k0 + row) * ld + rowbase + ch * 8);
            uint32_t dst = tb + (uint32_t)(row * 256 + ((ch ^ (row & 7)) << 4));
            asm volatile("cp.async.cg.shared.global [%0], [%1], 16;"
                         :: "r"(dst), "l"(g) : "memory");
        }
    }
}

// EPI: 0 = fp32 (+bias, optional accumulate), 2 = fp16 (*scale, +bias)
template<bool ATR, bool BTR, int EPI, bool SEG>
__global__ __launch_bounds__(128, 2)
void mma_gemm(const fp16* __restrict__ A_, long lda, long bsA, unsigned zmA,
              const fp16* __restrict__ B0, const fp16* __restrict__ B1,
              const fp16* __restrict__ B2, long ldb, long bsB,
              float* __restrict__ Cf, fp16* __restrict__ Ch,
              long ldc, long bsC,
              const float* __restrict__ bias, const float* __restrict__ scale,
              int K, int accum)
{
    extern __shared__ char smem[];
    const uint32_t sb = smem_u32(smem);
    const int tid = threadIdx.x;
    const int wid = tid >> 5, lane = tid & 31;
    const int warp_m = wid & 1, warp_n = wid >> 1;
    const long m0 = (long)blockIdx.y * 128, n0 = (long)blockIdx.x * 128;
    const long zA = (long)(blockIdx.z & zmA) * bsA, zB = (long)blockIdx.z * bsB;
    A_ += zA;
    B0 += zB;  B1 += zB;  B2 += zB;

    float d[4][8][4];
    #pragma unroll
    for (int i = 0; i < 4; i++)
        #pragma unroll
        for (int j = 0; j < 8; j++)
            #pragma unroll
            for (int q = 0; q < 4; q++) d[i][j][q] = 0.f;

    const int NC = K >> 6;

    auto loadstage = [&](int i) {
        const int s = i % STAGES;
        const long k0 = (long)i * 64;
        const fp16* Bp = B0;
        long kb = k0;
        if (SEG) {
            int seg = (int)(k0 >> 9);
            kb = k0 & 511;
            Bp = (seg == 0) ? B0 : (seg == 1) ? B1 : B2;
        }
        uint32_t tb = sb + (uint32_t)s * STGB;
        load_tile<ATR>(tb,         A_, m0, lda, k0, tid);
        load_tile<BTR>(tb + TILEB, Bp, n0, ldb, kb, tid);
        asm volatile("cp.async.commit_group;" ::: "memory");
    };

    for (int i = 0; i < STAGES - 1; i++) {
        if (i < NC) loadstage(i);
        else        asm volatile("cp.async.commit_group;" ::: "memory");
    }

    for (int i = 0; i < NC; i++) {
        asm volatile("cp.async.wait_group %0;" :: "n"(STAGES - 2) : "memory");
        __syncthreads();
        if (i + STAGES - 1 < NC) loadstage(i + STAGES - 1);
        else                     asm volatile("cp.async.commit_group;" ::: "memory");

        const int s = i % STAGES;
        const uint32_t bA = sb + (uint32_t)s * STGB;
        const uint32_t bB = bA + TILEB;

        #pragma unroll
        for (int ks = 0; ks < 4; ks++) {
            uint32_t ah[4][4];
            #pragma unroll
            for (int tm = 0; tm < 4; tm++) {
                if (!ATR) {
                    int row = warp_m * 64 + tm * 16 + (lane & 15);
                    int ch  = ks * 2 + (lane >> 4);
                    uint32_t off = (uint32_t)(row * 128 + ((ch ^ (row & 7)) << 4));
                    ldsm_x4(ah[tm], bA + off);
                } else {
                    int krow = ks * 16 + (lane & 7) + ((lane >> 4) << 3);
                    int mch  = ((warp_m * 64 + tm * 16) >> 3) + ((lane >> 3) & 1);
                    uint32_t off = (uint32_t)(krow * 256 + ((mch ^ (krow & 7)) << 4));
                    ldsm_x4_t(ah[tm], bA + off);
                }
            }
            uint32_t bh[4][4];
            #pragma unroll
            for (int tp = 0; tp < 4; tp++) {
                if (!BTR) {
                    int row = warp_n * 64 + tp * 16 + (lane & 7) + ((lane >> 4) << 3);
                    int ch  = ks * 2 + ((lane >> 3) & 1);
                    uint32_t off = (uint32_t)(row * 128 + ((ch ^ (row & 7)) << 4));
                    ldsm_x4(bh[tp], bB + off);
                } else {
                    int krow = ks * 16 + (lane & 7) + ((lane >> 3) & 1) * 8;
                    int nch  = ((warp_n * 64 + tp * 16) >> 3) + (lane >> 4);
                    uint32_t off = (uint32_t)(krow * 256 + ((nch ^ (krow & 7)) << 4));
                    ldsm_x4_t(bh[tp], bB + off);
                }
            }
            #pragma unroll
            for (int tm = 0; tm < 4; tm++)
                #pragma unroll
                for (int tp = 0; tp < 4; tp++) {
                    mma16816(d[tm][tp * 2 + 0], ah[tm], bh[tp] + 0);
                    mma16816(d[tm][tp * 2 + 1], ah[tm], bh[tp] + 2);
                }
        }
        __syncthreads();
    }

    if (EPI == 0) {
        float* Cb = Cf + (long)blockIdx.z * bsC;
        #pragma unroll
        for (int tm = 0; tm < 4; tm++) {
            const long m = m0 + warp_m * 64 + tm * 16 + (lane >> 2);
            const float bs0 = bias ? bias[m]     : 0.f;
            const float bs1 = bias ? bias[m + 8] : 0.f;
            #pragma unroll
            for (int tn = 0; tn < 8; tn++) {
                const long n = n0 + warp_n * 64 + tn * 8 + (lane & 3) * 2;
                float2 v0 = make_float2(d[tm][tn][0] + bs0, d[tm][tn][1] + bs0);
                float2 v1 = make_float2(d[tm][tn][2] + bs1, d[tm][tn][3] + bs1);
                if (accum) {
                    float2 o0 = *(const float2*)&Cb[m * ldc + n];
                    float2 o1 = *(const float2*)&Cb[(m + 8) * ldc + n];
                    v0.x += o0.x;  v0.y += o0.y;
                    v1.x += o1.x;  v1.y += o1.y;
                }
                *(float2*)&Cb[m * ldc + n]       = v0;
                *(float2*)&Cb[(m + 8) * ldc + n] = v1;
            }
        }
    } else {
        fp16* Hb = Ch + (long)blockIdx.z * bsC;
        const float sc = scale ? *scale : 1.0f;
        #pragma unroll
        for (int tm = 0; tm < 4; tm++) {
            const long m = m0 + warp_m * 64 + tm * 16 + (lane >> 2);
            const float bs0 = bias ? bias[m]     : 0.f;
            const float bs1 = bias ? bias[m + 8] : 0.f;
            #pragma unroll
            for (int tn = 0; tn < 8; tn++) {
                const long n = n0 + warp_n * 64 + tn * 8 + (lane & 3) * 2;
                __half2 p0 = __floats2half2_rn(d[tm][tn][0] * sc + bs0,
                                               d[tm][tn][1] * sc + bs0);
                __half2 p1 = __floats2half2_rn(d[tm][tn][2] * sc + bs1,
                                               d[tm][tn][3] * sc + bs1);
                *(__half2*)&Hb[m * ldc + n]       = p0;
                *(__half2*)&Hb[(m + 8) * ldc + n] = p1;
            }
        }
    }
}

// ---------------- Winograd F(4x4,3x3) transforms -------------------------------
__global__ __launch_bounds__(256)
void wino_input4(const float* __restrict__ x, fp16* __restrict__ Vh,
                 fp16* __restrict__ xh) {
    long gid = (long)blockIdx.x * 256 + threadIdx.x;
    int tile = (int)(gid & (NT4 - 1));
    long r = gid >> 6;
    int ci = (int)(r & (CC - 1));
    int b  = (int)(r >> 9);
    int ty = tile >> 3, tx = tile & 7;
    const long xoff = ((long)b * CC + ci) * NN;
    const float* xb = x + xoff;
    const int h0 = 4 * ty - 1, w0 = 4 * tx - 1;

    float dd[6][6];
    #pragma unroll
    for (int i = 0; i < 6; i++) {
        int ih = h0 + i;
        #pragma unroll
        for (int j = 0; j < 6; j++) {
            int iw = w0 + j;
            dd[i][j] = ((unsigned)ih < HH && (unsigned)iw < WW) ? xb[ih * WW + iw] : 0.f;
        }
    }
    {
        fp16* xo = xh + xoff + (4 * ty) * WW + 4 * tx;
        #pragma unroll
        for (int i = 0; i < 4; i++) {
            __half2 p0 = __floats2half2_rn(dd[i + 1][1], dd[i + 1][2]);
            __half2 p1 = __floats2half2_rn(dd[i + 1][3], dd[i + 1][4]);
            *(__half2*)&xo[i * WW]     = p0;
            *(__half2*)&xo[i * WW + 2] = p1;
        }
    }
    float t[6][6];
    #pragma unroll
    for (int j = 0; j < 6; j++) {
        t[0][j] =  4.f*dd[0][j] - 5.f*dd[2][j] + dd[4][j];
        t[1][j] = -4.f*dd[1][j] - 4.f*dd[2][j] + dd[3][j] + dd[4][j];
        t[2][j] =  4.f*dd[1][j] - 4.f*dd[2][j] - dd[3][j] + dd[4][j];
        t[3][j] = -2.f*dd[1][j] -     dd[2][j] + 2.f*dd[3][j] + dd[4][j];
        t[4][j] =  2.f*dd[1][j] -     dd[2][j] - 2.f*dd[3][j] + dd[4][j];
        t[5][j] =  4.f*dd[1][j] - 5.f*dd[3][j] + dd[5][j];
    }
    const long tcol = (long)b * NT4 + tile;
    #pragma unroll
    for (int i = 0; i < 6; i++) {
        float V0 =  4.f*t[i][0] - 5.f*t[i][2] + t[i][4];
        float V1 = -4.f*t[i][1] - 4.f*t[i][2] + t[i][3] + t[i][4];
        float V2 =  4.f*t[i][1] - 4.f*t[i][2] - t[i][3] + t[i][4];
        float V3 = -2.f*t[i][1] -     t[i][2] + 2.f*t[i][3] + t[i][4];
        float V4 =  2.f*t[i][1] -     t[i][2] - 2.f*t[i][3] + t[i][4];
        float V5 =  4.f*t[i][1] - 5.f*t[i][3] + t[i][5];
        float Vv[6] = {V0, V1, V2, V3, V4, V5};
        #pragma unroll
        for (int j = 0; j < 6; j++)
            Vh[((long)(i * 6 + j) * CC + ci) * TCOLS + tcol] = __float2half_rn(Vv[j]);
    }
}

__global__ __launch_bounds__(256)
void wino_weight4(const float* __restrict__ w1, const float* __restrict__ w2,
                  const float* __restrict__ w3, fp16* __restrict__ Uh) {
    const int conv = blockIdx.y;
    const float* w = (conv == 0) ? w1 : (conv == 1) ? w2 : w3;
    const int co_base = conv * CC;
    int gid = blockIdx.x * 256 + threadIdx.x;
    int ci = gid & (CC - 1), co = gid >> 9;
    const float* g = w + (long)gid * 9;
    float t2[6][3];
    #pragma unroll
    for (int j = 0; j < 3; j++) {
        float g0 = g[0 * 3 + j], g1 = g[1 * 3 + j], g2 = g[2 * 3 + j];
        t2[0][j] = 0.25f * g0;
        t2[1][j] = (-g0 - g1 - g2) * (1.f / 6.f);
        t2[2][j] = (-g0 + g1 - g2) * (1.f / 6.f);
        t2[3][j] = g0 * (1.f / 24.f) + g1 * (1.f / 12.f) + g2 * (1.f / 6.f);
        t2[4][j] = g0 * (1.f / 24.f) - g1 * (1.f / 12.f) + g2 * (1.f / 6.f);
        t2[5][j] = g2;
    }
    #pragma unroll
    for (int i = 0; i < 6; i++) {
        float a = t2[i][0], bq = t2[i][1], c = t2[i][2];
        float Uv[6];
        Uv[0] = 0.25f * a;
        Uv[1] = (-a - bq - c) * (1.f / 6.f);
        Uv[2] = (-a + bq - c) * (1.f / 6.f);
        Uv[3] = a * (1.f / 24.f) + bq * (1.f / 12.f) + c * (1.f / 6.f);
        Uv[4] = a * (1.f / 24.f) - bq * (1.f / 12.f) + c * (1.f / 6.f);
        Uv[5] = c;
        #pragma unroll
        for (int j = 0; j < 6; j++)
            Uh[((long)(i * 6 + j) * C3 + co_base + co) * CC + ci] = __float2half_rn(Uv[j]);
    }
}

__global__ __launch_bounds__(256)
void wino_output4(const fp16* __restrict__ M,
                  const float* __restrict__ b1, const float* __restrict__ b2,
                  const float* __restrict__ b3,
                  fp16* __restrict__ Ah, fp16* __restrict__ Bmh,
                  fp16* __restrict__ Dh) {
    long gid = (long)blockIdx.x * 256 + threadIdx.x;
    int tile = (int)(gid & (NT4 - 1));
    long r = gid >> 6;
    int co3 = (int)(r % C3);
    int b   = (int)(r / C3);
    const long tcol = (long)b * NT4 + tile;
    const int seg = co3 >> 9, co = co3 & (CC - 1);

    float m[6][6];
    #pragma unroll
    for (int c = 0; c < 36; c++)
        m[c / 6][c % 6] = __half2float(M[((long)c * C3 + co3) * TCOLS + tcol]);

    float s[4][6];
    #pragma unroll
    for (int j = 0; j < 6; j++) {
        s[0][j] = m[0][j] + m[1][j] + m[2][j] + m[3][j] + m[4][j];
        s[1][j] = m[1][j] - m[2][j] + 2.f * (m[3][j] - m[4][j]);
        s[2][j] = m[1][j] + m[2][j] + 4.f * (m[3][j] + m[4][j]);
        s[3][j] = m[1][j] - m[2][j] + 8.f * (m[3][j] - m[4][j]) + m[5][j];
    }
    const float bs = (seg == 0) ? b1[co] : (seg == 1) ? b2[co] : b3[co];
    fp16* O = (seg == 0) ? Ah : (seg == 1) ? Bmh : Dh;
    int ty = tile >> 3, tx = tile & 7;
    long base = ((long)b * CC + co) * NN + (4 * ty) * WW + 4 * tx;
    #pragma unroll
    for (int i = 0; i < 4; i++) {
        float Y[4];
        Y[0] = s[i][0] + s[i][1] + s[i][2] + s[i][3] + s[i][4] + bs;
        Y[1] = s[i][1] - s[i][2] + 2.f * (s[i][3] - s[i][4]) + bs;
        Y[2] = s[i][1] + s[i][2] + 4.f * (s[i][3] + s[i][4]) + bs;
        Y[3] = s[i][1] - s[i][2] + 8.f * (s[i][3] - s[i][4]) + s[i][5] + bs;
        long ro = base + i * WW;
        #pragma unroll
        for (int j = 0; j < 4; j++)
            O[ro + j] = __float2half_rn(Y[j]);
    }
}

// ---------------- fp32 -> fp16 convert ------------------------------------------
__global__ void cvt_kernel(const float* __restrict__ in, fp16* __restrict__ oh) {
    long g = (long)blockIdx.x * 256 + threadIdx.x;
    oh[g] = __float2half_rn(in[g]);
}

// ---------------- softmax -------------------------------------------------------
__device__ __forceinline__ float warpMax(float v) {
    #pragma unroll
    for (int o = 16; o > 0; o >>= 1) v = fmaxf(v, __shfl_xor_sync(0xffffffffu, v, o));
    return v;
}
__device__ __forceinline__ float warpSum(float v) {
    #pragma unroll
    for (int o = 16; o > 0; o >>= 1) v += __shfl_xor_sync(0xffffffffu, v, o);
    return v;
}

template<int LEN>
__global__ __launch_bounds__(256)
void softmax_fp16(const float* __restrict__ buf, fp16* __restrict__ oh) {
    constexpr int V = LEN / 256;
    const long base = (long)blockIdx.x * LEN;
    const float* row = buf + base;
    const int tid = threadIdx.x, lane = tid & 31, wid = tid >> 5;
    __shared__ float sred[8];
    float v[V];
    float mx = -3.0e38f;
    #pragma unroll
    for (int j = 0; j < V; j++) { v[j] = row[tid + j * 256]; mx = fmaxf(mx, v[j]); }
    mx = warpMax(mx);
    if (lane == 0) sred[wid] = mx;
    __syncthreads();
    if (tid == 0) {
        float m = sred[0];
        #pragma unroll
        for (int i = 1; i < 8; i++) m = fmaxf(m, sred[i]);
        sred[0] = m;
    }
    __syncthreads();
    mx = sred[0];
    __syncthreads();
    float s = 0.f;
    #pragma unroll
    for (int j = 0; j < V; j++) { v[j] = __expf(v[j] - mx); s += v[j]; }
    s = warpSum(s);
    if (lane == 0) sred[wid] = s;
    __syncthreads();
    if (tid == 0) {
        float m = 0.f;
        #pragma unroll
        for (int i = 0; i < 8; i++) m += sred[i];
        sred[0] = m;
    }
    __syncthreads();
    const float inv = 1.0f / sred[0];
    #pragma unroll
    for (int j = 0; j < V; j++)
        oh[base + tid + j * 256] = __float2half_rn(v[j] * inv);
}

// ---------------- launch --------------------------------------------------------
extern "C" void kernel_launch(void* const* d_in, const int* in_sizes, int n_in,
                              void* d_out, int out_size) {
    const float* x     = (const float*)d_in[0];
    const float* w1    = (const float*)d_in[1];
    const float* b1    = (const float*)d_in[2];
    const float* w2    = (const float*)d_in[3];
    const float* b2    = (const float*)d_in[4];
    const float* w3    = (const float*)d_in[5];
    const float* b3    = (const float*)d_in[6];
    const float* alpha = (const float*)d_in[7];
    const float* beta  = (const float*)d_in[8];
    const float* wf    = (const float*)d_in[9];
    const float* bf    = (const float*)d_in[10];
    float* out = (float*)d_out;

    cudaFuncSetAttribute(mma_gemm<false,true, 2,false>, cudaFuncAttributeMaxDynamicSharedMemorySize, GEMM_SMEM);
    cudaFuncSetAttribute(mma_gemm<true, true, 0,false>, cudaFuncAttributeMaxDynamicSharedMemorySize, GEMM_SMEM);
    cudaFuncSetAttribute(mma_gemm<false,false,2,false>, cudaFuncAttributeMaxDynamicSharedMemorySize, GEMM_SMEM);
    cudaFuncSetAttribute(mma_gemm<false,false,0,false>, cudaFuncAttributeMaxDynamicSharedMemorySize, GEMM_SMEM);
    cudaFuncSetAttribute(mma_gemm<true, true, 2,false>, cudaFuncAttributeMaxDynamicSharedMemorySize, GEMM_SMEM);
    cudaFuncSetAttribute(mma_gemm<false,true, 0,false>, cudaFuncAttributeMaxDynamicSharedMemorySize, GEMM_SMEM);
    cudaFuncSetAttribute(mma_gemm<false,true, 0,true >, cudaFuncAttributeMaxDynamicSharedMemorySize, GEMM_SMEM);

    fp16 *Vh, *Uh, *Mw16, *wfh, *Ah, *Bmh, *Dh, *xh, *Mh, *Sh, *spath, *chanh;
    float *Mb, *Sb;
    cudaGetSymbolAddress((void**)&Vh, g_Vh);
    cudaGetSymbolAddress((void**)&Uh, g_Uh);
    cudaGetSymbolAddress((void**)&Mw16, g_Mw);
    cudaGetSymbolAddress((void**)&wfh, g_wfh);
    cudaGetSymbolAddress((void**)&Ah,  g_Ah);
    cudaGetSymbolAddress((void**)&Bmh, g_Bmh);
    cudaGetSymbolAddress((void**)&Dh,  g_Dh);
    cudaGetSymbolAddress((void**)&xh,  g_xh);
    cudaGetSymbolAddress((void**)&Mb,  g_M);
    cudaGetSymbolAddress((void**)&Mh,  g_Mh);
    cudaGetSymbolAddress((void**)&Sb,  g_S);
    cudaGetSymbolAddress((void**)&Sh,  g_Sh);
    cudaGetSymbolAddress((void**)&spath, g_spath);
    cudaGetSymbolAddress((void**)&chanh, g_chanh);

    const long sX  = (long)CC * NN;
    const long sM  = (long)NN * NN;
    const long sS  = (long)CC * CC;
    const long sVt = (long)CC * TCOLS;
    const long sUt = (long)C3 * CC;
    const long sMwt = (long)C3 * TCOLS;
    const unsigned ZALL = 0xFFFFFFFFu;

    cudaStream_t s2;
    cudaStreamCreateWithFlags(&s2, cudaStreamNonBlocking);
    cudaEvent_t evFork0, evFork, evJoin, evU;
    cudaEventCreateWithFlags(&evFork0, cudaEventDisableTiming);
    cudaEventCreateWithFlags(&evFork,  cudaEventDisableTiming);
    cudaEventCreateWithFlags(&evJoin,  cudaEventDisableTiming);
    cudaEventCreateWithFlags(&evU,     cudaEventDisableTiming);

    // fork s2 into the capture FIRST (legal fork: event recorded on capture
    // stream, side stream waits it before any launch).
    cudaEventRecord(evFork0, 0);
    cudaStreamWaitEvent(s2, evFork0, 0);

    // --- side stream: weight-side prep (independent of x) ---
    wino_weight4<<<dim3(CC * CC / 256, 3), 256, 0, s2>>>(w1, w2, w3, Uh);
    cvt_kernel<<<CC * C3 / 256, 256, 0, s2>>>(wf, wfh);
    cudaEventRecord(evU, s2);

    // --- main: input transform (also produces xh), concurrent with weight prep ---
    wino_input4<<<(unsigned)((long)BB * CC * NT4 / 256), 256>>>(x, Vh, xh);
    cudaEventRecord(evFork, 0);

    // --- side stream: S-chain + fuse_x (needs xh from main, wfh local) ---
    cudaStreamWaitEvent(s2, evFork, 0);
    {
        dim3 g(CC / 128, CC / 128, BB);
        mma_gemm<false,false,0,false><<<g, 128, GEMM_SMEM, s2>>>(
            xh, NN, sX, ZALL, xh, xh, xh, NN, sX,
            Sb, nullptr, CC, sS, nullptr, nullptr, NN, 0);
    }
    softmax_fp16<CC><<<BB * CC, 256, 0, s2>>>(Sb, Sh);
    {
        dim3 g(NN / 128, CC / 128, BB);
        mma_gemm<true,true,2,false><<<g, 128, GEMM_SMEM, s2>>>(
            Sh, CC, sS, ZALL, xh, xh, xh, NN, sX,
            nullptr, chanh, NN, sX, nullptr, beta, CC, 0);
    }
    // fuse_x: out = bf + wf[:, 0:512] @ x
    {
        dim3 g(NN / 128, CC / 128, BB);
        mma_gemm<false,true,0,false><<<g, 128, GEMM_SMEM, s2>>>(
            wfh, C3, 0, ZALL, xh, xh, xh, NN, sX,
            out, nullptr, NN, sX, bf, nullptr, CC, 0);
    }
    cudaEventRecord(evJoin, s2);

    // --- main: conv chain (needs Uh from side stream) ---
    cudaStreamWaitEvent(0, evU, 0);
    {
        dim3 g(TCOLS / 128, C3 / 128, TAPS);
        mma_gemm<false,true,2,false><<<g, 128, GEMM_SMEM>>>(
            Uh, CC, sUt, ZALL, Vh, Vh, Vh, TCOLS, sVt,
            nullptr, Mw16, TCOLS, sMwt, nullptr, nullptr, CC, 0);
        wino_output4<<<(unsigned)((long)BB * C3 * NT4 / 256), 256>>>(
            Mw16, b1, b2, b3, Ah, Bmh, Dh);
    }
    {
        dim3 g(NN / 128, NN / 128, BB);
        mma_gemm<true,true,0,false><<<g, 128, GEMM_SMEM>>>(
            Ah, NN, sX, ZALL, Bmh, Bmh, Bmh, NN, sX,
            Mb, nullptr, NN, sM, nullptr, nullptr, CC, 0);
    }
    softmax_fp16<NN><<<BB * NN, 256>>>(Mb, Mh);
    {
        dim3 g(NN / 128, CC / 128, BB);
        mma_gemm<false,false,2,false><<<g, 128, GEMM_SMEM>>>(
            Dh, NN, sX, ZALL, Mh, Mh, Mh, NN, sM,
            nullptr, spath, NN, sX, nullptr, alpha, NN, 0);
    }

    // join: final fuse needs chanh + out(fuse_x) from the side stream
    cudaStreamWaitEvent(0, evJoin, 0);

    // final fuse: out += wf[:, 512:1024]@spat' + wf[:, 1024:1536]@chan'
    {
        dim3 g(NN / 128, CC / 128, BB);
        mma_gemm<false,true,0,true><<<g, 128, GEMM_SMEM>>>(
            wfh + CC, C3, 0, ZALL, spath, chanh, chanh, NN, sX,
            out, nullptr, NN, sX, nullptr, nullptr, 2 * CC, 1);
    }
    // streams/events are host objects (no device allocation); intentionally not
    // destroyed while the surrounding graph capture may still reference them.
}

// round 17
// speedup vs baseline: 1.0309x; 1.0309x over previous
#include <cuda_runtime.h>
#include <cuda_fp16.h>
#include <cstdint>

#define BB 16
#define CC 512
#define HH 32
#define WW 32
#define NN 1024
#define C3 1536
#define NT4 64
#define TCOLS 1024
#define TAPS 36

typedef __half fp16;

// ---------------- scratch (device globals) -----------------------------------
__device__ fp16 g_Vh[(size_t)TAPS * CC * TCOLS];
__device__ fp16 g_Uh[(size_t)TAPS * C3 * CC];
__device__ fp16 g_Mw[(size_t)TAPS * C3 * TCOLS];
__device__ fp16 g_wfh[CC * C3];
__device__ fp16 g_Ah[(size_t)BB * CC * NN];
__device__ fp16 g_Bmh[(size_t)BB * CC * NN];
__device__ fp16 g_Dh[(size_t)BB * CC * NN];
__device__ fp16 g_xh[(size_t)BB * CC * NN];
__device__ float g_M[(size_t)BB * NN * NN];
__device__ fp16 g_Mh[(size_t)BB * NN * NN];
__device__ float g_S[(size_t)BB * CC * CC];
__device__ fp16 g_Sh[(size_t)BB * CC * CC];
__device__ fp16 g_spath[(size_t)BB * CC * NN];
__device__ fp16 g_chanh[(size_t)BB * CC * NN];

// ---------------- helpers ------------------------------------------------------
__device__ __forceinline__ uint32_t smem_u32(const void* p) {
    uint32_t a;
    asm("{ .reg .u64 t; cvta.to.shared.u64 t, %1; cvt.u32.u64 %0, t; }"
        : "=r"(a) : "l"(p));
    return a;
}
__device__ __forceinline__ void ldsm_x4(uint32_t* r, uint32_t addr) {
    asm volatile("ldmatrix.sync.aligned.m8n8.x4.shared.b16 {%0,%1,%2,%3}, [%4];"
                 : "=r"(r[0]), "=r"(r[1]), "=r"(r[2]), "=r"(r[3]) : "r"(addr));
}
__device__ __forceinline__ void ldsm_x4_t(uint32_t* r, uint32_t addr) {
    asm volatile("ldmatrix.sync.aligned.m8n8.x4.trans.shared.b16 {%0,%1,%2,%3}, [%4];"
                 : "=r"(r[0]), "=r"(r[1]), "=r"(r[2]), "=r"(r[3]) : "r"(addr));
}
__device__ __forceinline__ void mma16816(float* d, const uint32_t* a, const uint32_t* b) {
    asm volatile("mma.sync.aligned.m16n8k16.row.col.f32.f16.f16.f32 "
                 "{%0,%1,%2,%3}, {%4,%5,%6,%7}, {%8,%9}, {%0,%1,%2,%3};"
                 : "+f"(d[0]), "+f"(d[1]), "+f"(d[2]), "+f"(d[3])
                 : "r"(a[0]), "r"(a[1]), "r"(a[2]), "r"(a[3]), "r"(b[0]), "r"(b[1]));
}

// ---------------- GEMM ----------------------------------------------------------
// Block tile 128x128, BK=64, 128 threads (4 warps 2x2), warp tile 64x64.
// 3 stages x 32 KB = 96 KB/CTA; 2 CTAs co-resident.
#define TILEB 16384
#define STGB  (2 * TILEB)                // 32 KB
#define STAGES 3
#define GEMM_SMEM (STAGES * STGB)        // 96 KB

template<bool TR>
__device__ __forceinline__ void load_tile(uint32_t tb, const fp16* __restrict__ S,
                                          long rowbase, long ld, long k0, int tid) {
    if (!TR) {
        #pragma unroll
        for (int p = 0; p < 8; p++) {
            int row = (tid >> 3) + p * 16;
            int ch  = tid & 7;
            const void* g = (const void*)(S + (rowbase + row) * ld + k0 + ch * 8);
            uint32_t dst = tb + (uint32_t)(row * 128 + ((ch ^ (row & 7)) << 4));
            asm volatile("cp.async.cg.shared.global [%0], [%1], 16;"
                         :: "r"(dst), "l"(g) : "memory");
        }
    } else {
        #pragma unroll
        for (int p = 0; p < 8; p++) {
            int row = (tid >> 4) + p * 8;
            int ch  = tid & 15;
            const void* g = (const void*)(S + (k0 + row) * ld + rowbase + ch * 8);
            uint32_t dst = tb + (uint32_t)(row * 256 + ((ch ^ (row & 7)) << 4));
            asm volatile("cp.async.cg.shared.global [%0], [%1], 16;"
                         :: "r"(dst), "l"(g) : "memory");
        }
    }
}

// EPI: 0 = fp32 (+bias), 2 = fp16 (*scale, +bias)
template<bool ATR, bool BTR, int EPI, bool SEG>
__global__ __launch_bounds__(128, 2)
void mma_gemm(const fp16* __restrict__ A_, long lda, long bsA, unsigned zmA,
              const fp16* __restrict__ B0, const fp16* __restrict__ B1,
              const fp16* __restrict__ B2, long ldb, long bsB,
              float* __restrict__ Cf, fp16* __restrict__ Ch,
              long ldc, long bsC,
              const float* __restrict__ bias, const float* __restrict__ scale, int K)
{
    extern __shared__ char smem[];
    const uint32_t sb = smem_u32(smem);
    const int tid = threadIdx.x;
    const int wid = tid >> 5, lane = tid & 31;
    const int warp_m = wid & 1, warp_n = wid >> 1;
    const long m0 = (long)blockIdx.y * 128, n0 = (long)blockIdx.x * 128;
    const long zA = (long)(blockIdx.z & zmA) * bsA, zB = (long)blockIdx.z * bsB;
    A_ += zA;
    B0 += zB;  B1 += zB;  B2 += zB;

    float d[4][8][4];
    #pragma unroll
    for (int i = 0; i < 4; i++)
        #pragma unroll
        for (int j = 0; j < 8; j++)
            #pragma unroll
            for (int q = 0; q < 4; q++) d[i][j][q] = 0.f;

    const int NC = K >> 6;

    auto loadstage = [&](int i) {
        const int s = i % STAGES;
        const long k0 = (long)i * 64;
        const fp16* Bp = B0;
        long kb = k0;
        if (SEG) {
            int seg = (int)(k0 >> 9);
            kb = k0 & 511;
            Bp = (seg == 0) ? B0 : (seg == 1) ? B1 : B2;
        }
        uint32_t tb = sb + (uint32_t)s * STGB;
        load_tile<ATR>(tb,         A_, m0, lda, k0, tid);
        load_tile<BTR>(tb + TILEB, Bp, n0, ldb, kb, tid);
        asm volatile("cp.async.commit_group;" ::: "memory");
    };

    for (int i = 0; i < STAGES - 1; i++) {
        if (i < NC) loadstage(i);
        else        asm volatile("cp.async.commit_group;" ::: "memory");
    }

    for (int i = 0; i < NC; i++) {
        asm volatile("cp.async.wait_group %0;" :: "n"(STAGES - 2) : "memory");
        __syncthreads();
        if (i + STAGES - 1 < NC) loadstage(i + STAGES - 1);
        else                     asm volatile("cp.async.commit_group;" ::: "memory");

        const int s = i % STAGES;
        const uint32_t bA = sb + (uint32_t)s * STGB;
        const uint32_t bB = bA + TILEB;

        #pragma unroll
        for (int ks = 0; ks < 4; ks++) {
            uint32_t ah[4][4];
            #pragma unroll
            for (int tm = 0; tm < 4; tm++) {
                if (!ATR) {
                    int row = warp_m * 64 + tm * 16 + (lane & 15);
                    int ch  = ks * 2 + (lane >> 4);
                    uint32_t off = (uint32_t)(row * 128 + ((ch ^ (row & 7)) << 4));
                    ldsm_x4(ah[tm], bA + off);
                } else {
                    int krow = ks * 16 + (lane & 7) + ((lane >> 4) << 3);
                    int mch  = ((warp_m * 64 + tm * 16) >> 3) + ((lane >> 3) & 1);
                    uint32_t off = (uint32_t)(krow * 256 + ((mch ^ (krow & 7)) << 4));
                    ldsm_x4_t(ah[tm], bA + off);
                }
            }
            uint32_t bh[4][4];
            #pragma unroll
            for (int tp = 0; tp < 4; tp++) {
                if (!BTR) {
                    int row = warp_n * 64 + tp * 16 + (lane & 7) + ((lane >> 4) << 3);
                    int ch  = ks * 2 + ((lane >> 3) & 1);
                    uint32_t off = (uint32_t)(row * 128 + ((ch ^ (row & 7)) << 4));
                    ldsm_x4(bh[tp], bB + off);
                } else {
                    int krow = ks * 16 + (lane & 7) + ((lane >> 3) & 1) * 8;
                    int nch  = ((warp_n * 64 + tp * 16) >> 3) + (lane >> 4);
                    uint32_t off = (uint32_t)(krow * 256 + ((nch ^ (krow & 7)) << 4));
                    ldsm_x4_t(bh[tp], bB + off);
                }
            }
            #pragma unroll
            for (int tm = 0; tm < 4; tm++)
                #pragma unroll
                for (int tp = 0; tp < 4; tp++) {
                    mma16816(d[tm][tp * 2 + 0], ah[tm], bh[tp] + 0);
                    mma16816(d[tm][tp * 2 + 1], ah[tm], bh[tp] + 2);
                }
        }
        __syncthreads();
    }

    if (EPI == 0) {
        float* Cb = Cf + (long)blockIdx.z * bsC;
        #pragma unroll
        for (int tm = 0; tm < 4; tm++) {
            const long m = m0 + warp_m * 64 + tm * 16 + (lane >> 2);
            const float bs0 = bias ? bias[m]     : 0.f;
            const float bs1 = bias ? bias[m + 8] : 0.f;
            #pragma unroll
            for (int tn = 0; tn < 8; tn++) {
                const long n = n0 + warp_n * 64 + tn * 8 + (lane & 3) * 2;
                *(float2*)&Cb[m * ldc + n] =
                    make_float2(d[tm][tn][0] + bs0, d[tm][tn][1] + bs0);
                *(float2*)&Cb[(m + 8) * ldc + n] =
                    make_float2(d[tm][tn][2] + bs1, d[tm][tn][3] + bs1);
            }
        }
    } else {
        fp16* Hb = Ch + (long)blockIdx.z * bsC;
        const float sc = scale ? *scale : 1.0f;
        #pragma unroll
        for (int tm = 0; tm < 4; tm++) {
            const long m = m0 + warp_m * 64 + tm * 16 + (lane >> 2);
            const float bs0 = bias ? bias[m]     : 0.f;
            const float bs1 = bias ? bias[m + 8] : 0.f;
            #pragma unroll
            for (int tn = 0; tn < 8; tn++) {
                const long n = n0 + warp_n * 64 + tn * 8 + (lane & 3) * 2;
                __half2 p0 = __floats2half2_rn(d[tm][tn][0] * sc + bs0,
                                               d[tm][tn][1] * sc + bs0);
                __half2 p1 = __floats2half2_rn(d[tm][tn][2] * sc + bs1,
                                               d[tm][tn][3] * sc + bs1);
                *(__half2*)&Hb[m * ldc + n]       = p0;
                *(__half2*)&Hb[(m + 8) * ldc + n] = p1;
            }
        }
    }
}

// ---------------- Winograd F(4x4,3x3) transforms -------------------------------
__global__ __launch_bounds__(256)
void wino_input4(const float* __restrict__ x, fp16* __restrict__ Vh,
                 fp16* __restrict__ xh) {
    long gid = (long)blockIdx.x * 256 + threadIdx.x;
    int tile = (int)(gid & (NT4 - 1));
    long r = gid >> 6;
    int ci = (int)(r & (CC - 1));
    int b  = (int)(r >> 9);
    int ty = tile >> 3, tx = tile & 7;
    const long xoff = ((long)b * CC + ci) * NN;
    const float* xb = x + xoff;
    const int h0 = 4 * ty - 1, w0 = 4 * tx - 1;

    float dd[6][6];
    #pragma unroll
    for (int i = 0; i < 6; i++) {
        int ih = h0 + i;
        #pragma unroll
        for (int j = 0; j < 6; j++) {
            int iw = w0 + j;
            dd[i][j] = ((unsigned)ih < HH && (unsigned)iw < WW) ? xb[ih * WW + iw] : 0.f;
        }
    }
    {
        fp16* xo = xh + xoff + (4 * ty) * WW + 4 * tx;
        #pragma unroll
        for (int i = 0; i < 4; i++) {
            __half2 p0 = __floats2half2_rn(dd[i + 1][1], dd[i + 1][2]);
            __half2 p1 = __floats2half2_rn(dd[i + 1][3], dd[i + 1][4]);
            *(__half2*)&xo[i * WW]     = p0;
            *(__half2*)&xo[i * WW + 2] = p1;
        }
    }
    float t[6][6];
    #pragma unroll
    for (int j = 0; j < 6; j++) {
        t[0][j] =  4.f*dd[0][j] - 5.f*dd[2][j] + dd[4][j];
        t[1][j] = -4.f*dd[1][j] - 4.f*dd[2][j] + dd[3][j] + dd[4][j];
        t[2][j] =  4.f*dd[1][j] - 4.f*dd[2][j] - dd[3][j] + dd[4][j];
        t[3][j] = -2.f*dd[1][j] -     dd[2][j] + 2.f*dd[3][j] + dd[4][j];
        t[4][j] =  2.f*dd[1][j] -     dd[2][j] - 2.f*dd[3][j] + dd[4][j];
        t[5][j] =  4.f*dd[1][j] - 5.f*dd[3][j] + dd[5][j];
    }
    const long tcol = (long)b * NT4 + tile;
    #pragma unroll
    for (int i = 0; i < 6; i++) {
        float V0 =  4.f*t[i][0] - 5.f*t[i][2] + t[i][4];
        float V1 = -4.f*t[i][1] - 4.f*t[i][2] + t[i][3] + t[i][4];
        float V2 =  4.f*t[i][1] - 4.f*t[i][2] - t[i][3] + t[i][4];
        float V3 = -2.f*t[i][1] -     t[i][2] + 2.f*t[i][3] + t[i][4];
        float V4 =  2.f*t[i][1] -     t[i][2] - 2.f*t[i][3] + t[i][4];
        float V5 =  4.f*t[i][1] - 5.f*t[i][3] + t[i][5];
        float Vv[6] = {V0, V1, V2, V3, V4, V5};
        #pragma unroll
        for (int j = 0; j < 6; j++)
            Vh[((long)(i * 6 + j) * CC + ci) * TCOLS + tcol] = __float2half_rn(Vv[j]);
    }
}

__global__ __launch_bounds__(256)
void wino_weight4(const float* __restrict__ w1, const float* __restrict__ w2,
                  const float* __restrict__ w3, fp16* __restrict__ Uh) {
    const int conv = blockIdx.y;
    const float* w = (conv == 0) ? w1 : (conv == 1) ? w2 : w3;
    const int co_base = conv * CC;
    int gid = blockIdx.x * 256 + threadIdx.x;
    int ci = gid & (CC - 1), co = gid >> 9;
    const float* g = w + (long)gid * 9;
    float t2[6][3];
    #pragma unroll
    for (int j = 0; j < 3; j++) {
        float g0 = g[0 * 3 + j], g1 = g[1 * 3 + j], g2 = g[2 * 3 + j];
        t2[0][j] = 0.25f * g0;
        t2[1][j] = (-g0 - g1 - g2) * (1.f / 6.f);
        t2[2][j] = (-g0 + g1 - g2) * (1.f / 6.f);
        t2[3][j] = g0 * (1.f / 24.f) + g1 * (1.f / 12.f) + g2 * (1.f / 6.f);
        t2[4][j] = g0 * (1.f / 24.f) - g1 * (1.f / 12.f) + g2 * (1.f / 6.f);
        t2[5][j] = g2;
    }
    #pragma unroll
    for (int i = 0; i < 6; i++) {
        float a = t2[i][0], bq = t2[i][1], c = t2[i][2];
        float Uv[6];
        Uv[0] = 0.25f * a;
        Uv[1] = (-a - bq - c) * (1.f / 6.f);
        Uv[2] = (-a + bq - c) * (1.f / 6.f);
        Uv[3] = a * (1.f / 24.f) + bq * (1.f / 12.f) + c * (1.f / 6.f);
        Uv[4] = a * (1.f / 24.f) - bq * (1.f / 12.f) + c * (1.f / 6.f);
        Uv[5] = c;
        #pragma unroll
        for (int j = 0; j < 6; j++)
            Uh[((long)(i * 6 + j) * C3 + co_base + co) * CC + ci] = __float2half_rn(Uv[j]);
    }
}

__global__ __launch_bounds__(256)
void wino_output4(const fp16* __restrict__ M,
                  const float* __restrict__ b1, const float* __restrict__ b2,
                  const float* __restrict__ b3,
                  fp16* __restrict__ Ah, fp16* __restrict__ Bmh,
                  fp16* __restrict__ Dh) {
    long gid = (long)blockIdx.x * 256 + threadIdx.x;
    int tile = (int)(gid & (NT4 - 1));
    long r = gid >> 6;
    int co3 = (int)(r % C3);
    int b   = (int)(r / C3);
    const long tcol = (long)b * NT4 + tile;
    const int seg = co3 >> 9, co = co3 & (CC - 1);

    float m[6][6];
    #pragma unroll
    for (int c = 0; c < 36; c++)
        m[c / 6][c % 6] = __half2float(M[((long)c * C3 + co3) * TCOLS + tcol]);

    float s[4][6];
    #pragma unroll
    for (int j = 0; j < 6; j++) {
        s[0][j] = m[0][j] + m[1][j] + m[2][j] + m[3][j] + m[4][j];
        s[1][j] = m[1][j] - m[2][j] + 2.f * (m[3][j] - m[4][j]);
        s[2][j] = m[1][j] + m[2][j] + 4.f * (m[3][j] + m[4][j]);
        s[3][j] = m[1][j] - m[2][j] + 8.f * (m[3][j] - m[4][j]) + m[5][j];
    }
    const float bs = (seg == 0) ? b1[co] : (seg == 1) ? b2[co] : b3[co];
    fp16* O = (seg == 0) ? Ah : (seg == 1) ? Bmh : Dh;
    int ty = tile >> 3, tx = tile & 7;
    long base = ((long)b * CC + co) * NN + (4 * ty) * WW + 4 * tx;
    #pragma unroll
    for (int i = 0; i < 4; i++) {
        float Y[4];
        Y[0] = s[i][0] + s[i][1] + s[i][2] + s[i][3] + s[i][4] + bs;
        Y[1] = s[i][1] - s[i][2] + 2.f * (s[i][3] - s[i][4]) + bs;
        Y[2] = s[i][1] + s[i][2] + 4.f * (s[i][3] + s[i][4]) + bs;
        Y[3] = s[i][1] - s[i][2] + 8.f * (s[i][3] - s[i][4]) + s[i][5] + bs;
        long ro = base + i * WW;
        #pragma unroll
        for (int j = 0; j < 4; j++)
            O[ro + j] = __float2half_rn(Y[j]);
    }
}

// ---------------- fp32 -> fp16 convert ------------------------------------------
__global__ void cvt_kernel(const float* __restrict__ in, fp16* __restrict__ oh) {
    long g = (long)blockIdx.x * 256 + threadIdx.x;
    oh[g] = __float2half_rn(in[g]);
}

// ---------------- softmax -------------------------------------------------------
__device__ __forceinline__ float warpMax(float v) {
    #pragma unroll
    for (int o = 16; o > 0; o >>= 1) v = fmaxf(v, __shfl_xor_sync(0xffffffffu, v, o));
    return v;
}
__device__ __forceinline__ float warpSum(float v) {
    #pragma unroll
    for (int o = 16; o > 0; o >>= 1) v += __shfl_xor_sync(0xffffffffu, v, o);
    return v;
}

template<int LEN>
__global__ __launch_bounds__(256)
void softmax_fp16(const float* __restrict__ buf, fp16* __restrict__ oh) {
    constexpr int V = LEN / 256;
    const long base = (long)blockIdx.x * LEN;
    const float* row = buf + base;
    const int tid = threadIdx.x, lane = tid & 31, wid = tid >> 5;
    __shared__ float sred[8];
    float v[V];
    float mx = -3.0e38f;
    #pragma unroll
    for (int j = 0; j < V; j++) { v[j] = row[tid + j * 256]; mx = fmaxf(mx, v[j]); }
    mx = warpMax(mx);
    if (lane == 0) sred[wid] = mx;
    __syncthreads();
    if (tid == 0) {
        float m = sred[0];
        #pragma unroll
        for (int i = 1; i < 8; i++) m = fmaxf(m, sred[i]);
        sred[0] = m;
    }
    __syncthreads();
    mx = sred[0];
    __syncthreads();
    float s = 0.f;
    #pragma unroll
    for (int j = 0; j < V; j++) { v[j] = __expf(v[j] - mx); s += v[j]; }
    s = warpSum(s);
    if (lane == 0) sred[wid] = s;
    __syncthreads();
    if (tid == 0) {
        float m = 0.f;
        #pragma unroll
        for (int i = 0; i < 8; i++) m += sred[i];
        sred[0] = m;
    }
    __syncthreads();
    const float inv = 1.0f / sred[0];
    #pragma unroll
    for (int j = 0; j < V; j++)
        oh[base + tid + j * 256] = __float2half_rn(v[j] * inv);
}

// ---------------- launch --------------------------------------------------------
extern "C" void kernel_launch(void* const* d_in, const int* in_sizes, int n_in,
                              void* d_out, int out_size) {
    const float* x     = (const float*)d_in[0];
    const float* w1    = (const float*)d_in[1];
    const float* b1    = (const float*)d_in[2];
    const float* w2    = (const float*)d_in[3];
    const float* b2    = (const float*)d_in[4];
    const float* w3    = (const float*)d_in[5];
    const float* b3    = (const float*)d_in[6];
    const float* alpha = (const float*)d_in[7];
    const float* beta  = (const float*)d_in[8];
    const float* wf    = (const float*)d_in[9];
    const float* bf    = (const float*)d_in[10];
    float* out = (float*)d_out;

    cudaFuncSetAttribute(mma_gemm<false,true, 2,false>, cudaFuncAttributeMaxDynamicSharedMemorySize, GEMM_SMEM);
    cudaFuncSetAttribute(mma_gemm<true, true, 0,false>, cudaFuncAttributeMaxDynamicSharedMemorySize, GEMM_SMEM);
    cudaFuncSetAttribute(mma_gemm<false,false,2,false>, cudaFuncAttributeMaxDynamicSharedMemorySize, GEMM_SMEM);
    cudaFuncSetAttribute(mma_gemm<false,false,0,false>, cudaFuncAttributeMaxDynamicSharedMemorySize, GEMM_SMEM);
    cudaFuncSetAttribute(mma_gemm<true, true, 2,false>, cudaFuncAttributeMaxDynamicSharedMemorySize, GEMM_SMEM);
    cudaFuncSetAttribute(mma_gemm<false,true, 0,true >, cudaFuncAttributeMaxDynamicSharedMemorySize, GEMM_SMEM);

    fp16 *Vh, *Uh, *Mw16, *wfh, *Ah, *Bmh, *Dh, *xh, *Mh, *Sh, *spath, *chanh;
    float *Mb, *Sb;
    cudaGetSymbolAddress((void**)&Vh, g_Vh);
    cudaGetSymbolAddress((void**)&Uh, g_Uh);
    cudaGetSymbolAddress((void**)&Mw16, g_Mw);
    cudaGetSymbolAddress((void**)&wfh, g_wfh);
    cudaGetSymbolAddress((void**)&Ah,  g_Ah);
    cudaGetSymbolAddress((void**)&Bmh, g_Bmh);
    cudaGetSymbolAddress((void**)&Dh,  g_Dh);
    cudaGetSymbolAddress((void**)&xh,  g_xh);
    cudaGetSymbolAddress((void**)&Mb,  g_M);
    cudaGetSymbolAddress((void**)&Mh,  g_Mh);
    cudaGetSymbolAddress((void**)&Sb,  g_S);
    cudaGetSymbolAddress((void**)&Sh,  g_Sh);
    cudaGetSymbolAddress((void**)&spath, g_spath);
    cudaGetSymbolAddress((void**)&chanh, g_chanh);

    const long sX  = (long)CC * NN;
    const long sM  = (long)NN * NN;
    const long sS  = (long)CC * CC;
    const long sVt = (long)CC * TCOLS;
    const long sUt = (long)C3 * CC;
    const long sMwt = (long)C3 * TCOLS;
    const unsigned ZALL = 0xFFFFFFFFu;

    cudaStream_t s2;
    cudaStreamCreateWithFlags(&s2, cudaStreamNonBlocking);
    cudaEvent_t evFork0, evFork, evJoin, evU;
    cudaEventCreateWithFlags(&evFork0, cudaEventDisableTiming);
    cudaEventCreateWithFlags(&evFork,  cudaEventDisableTiming);
    cudaEventCreateWithFlags(&evJoin,  cudaEventDisableTiming);
    cudaEventCreateWithFlags(&evU,     cudaEventDisableTiming);

    // fork s2 into the capture first (legal fork), then launch weight prep on it
    cudaEventRecord(evFork0, 0);
    cudaStreamWaitEvent(s2, evFork0, 0);

    // --- side stream: weight-side prep (independent of x) ---
    wino_weight4<<<dim3(CC * CC / 256, 3), 256, 0, s2>>>(w1, w2, w3, Uh);
    cvt_kernel<<<CC * C3 / 256, 256, 0, s2>>>(wf, wfh);
    cudaEventRecord(evU, s2);

    // --- main: input transform (also produces xh), concurrent with weight prep ---
    wino_input4<<<(unsigned)((long)BB * CC * NT4 / 256), 256>>>(x, Vh, xh);
    cudaEventRecord(evFork, 0);

    // --- side stream: S-chain only (needs xh) ---
    cudaStreamWaitEvent(s2, evFork, 0);
    {
        dim3 g(CC / 128, CC / 128, BB);
        mma_gemm<false,false,0,false><<<g, 128, GEMM_SMEM, s2>>>(
            xh, NN, sX, ZALL, xh, xh, xh, NN, sX,
            Sb, nullptr, CC, sS, nullptr, nullptr, NN);
    }
    softmax_fp16<CC><<<BB * CC, 256, 0, s2>>>(Sb, Sh);
    {
        dim3 g(NN / 128, CC / 128, BB);
        mma_gemm<true,true,2,false><<<g, 128, GEMM_SMEM, s2>>>(
            Sh, CC, sS, ZALL, xh, xh, xh, NN, sX,
            nullptr, chanh, NN, sX, nullptr, beta, CC);
    }
    cudaEventRecord(evJoin, s2);

    // --- main: conv chain (needs Uh from side stream) ---
    cudaStreamWaitEvent(0, evU, 0);
    {
        dim3 g(TCOLS / 128, C3 / 128, TAPS);
        mma_gemm<false,true,2,false><<<g, 128, GEMM_SMEM>>>(
            Uh, CC, sUt, ZALL, Vh, Vh, Vh, TCOLS, sVt,
            nullptr, Mw16, TCOLS, sMwt, nullptr, nullptr, CC);
        wino_output4<<<(unsigned)((long)BB * C3 * NT4 / 256), 256>>>(
            Mw16, b1, b2, b3, Ah, Bmh, Dh);
    }
    {
        dim3 g(NN / 128, NN / 128, BB);
        mma_gemm<true,true,0,false><<<g, 128, GEMM_SMEM>>>(
            Ah, NN, sX, ZALL, Bmh, Bmh, Bmh, NN, sX,
            Mb, nullptr, NN, sM, nullptr, nullptr, CC);
    }
    softmax_fp16<NN><<<BB * NN, 256>>>(Mb, Mh);
    {
        dim3 g(NN / 128, CC / 128, BB);
        mma_gemm<false,false,2,false><<<g, 128, GEMM_SMEM>>>(
            Dh, NN, sX, ZALL, Mh, Mh, Mh, NN, sM,
            nullptr, spath, NN, sX, nullptr, alpha, NN);
    }

    // join: fuse needs chanh from the side stream
    cudaStreamWaitEvent(0, evJoin, 0);

    // fuse: out = bf + wf . [x; a*spat; b*chan]  (single segmented GEMM, K=1536)
    {
        dim3 g(NN / 128, CC / 128, BB);
        mma_gemm<false,true,0,true><<<g, 128, GEMM_SMEM>>>(
            wfh, C3, 0, ZALL, xh, spath, chanh, NN, sX,
            out, nullptr, NN, sX, bf, nullptr, C3);
    }
    // streams/events are host objects (no device allocation); intentionally not
    // destroyed while the surrounding graph capture may still reference them.
}